// round 1
// baseline (speedup 1.0000x reference)
#include <cuda_runtime.h>

// Precomputed conj-weight unit phasors: (cos w, sin w); conj applied at use site.
__device__ float2 g_w1c[16];     // [o][k]          o in 0..3, k = di*2+dj
__device__ float2 g_w2c[512];    // [c][di][dj][o]  o fastest (conflict-free smem reads)
__device__ float2 g_ffwc[2880];  // [n][j]          j contiguous per output n

__global__ void precompute_weights(const float* __restrict__ w1,
                                   const float* __restrict__ w2,
                                   const float* __restrict__ ffw) {
    int t = threadIdx.x;
    if (t < 16) {
        float s, c; sincosf(w1[t], &s, &c);
        g_w1c[t] = make_float2(c, s);
    }
    for (int i = t; i < 512; i += blockDim.x) {
        // conv2_w row-major [o][c][di][dj]: i = o*64 + (c*16+di*4+dj)
        int o = i >> 6, r = i & 63;
        float s, c; sincosf(w2[i], &s, &c);
        g_w2c[r * 8 + o] = make_float2(c, s);
    }
    for (int i = t; i < 2880; i += blockDim.x) {
        // ff_w row-major [j][n], j<288, n<10 -> store [n][j]
        int j = i / 10, n = i % 10;
        float s, c; sincosf(ffw[i], &s, &c);
        g_ffwc[n * 288 + j] = make_float2(c, s);
    }
}

__global__ __launch_bounds__(320, 5)
void ringnn_kernel(const float* __restrict__ x, float* __restrict__ out) {
    __shared__ float2 s_z[784];    // e^{i x[pixel]}
    __shared__ float2 s_e1[784];   // conv1 output phasors, [c][i][j] = c*196 + i*14 + j
    __shared__ float2 s_f[288];    // conv2 output phasors, [(u*6+v)*8 + o]
    __shared__ float2 s_w1[16];
    __shared__ float2 s_w2[512];
    __shared__ float2 s_ffw[2880];

    const int tid = threadIdx.x;
    const int b = blockIdx.x;

    // Stage weights into smem (L1-resident after first block per SM; trivial cost)
    for (int i = tid; i < 16;   i += 320) s_w1[i]  = g_w1c[i];
    for (int i = tid; i < 512;  i += 320) s_w2[i]  = g_w2c[i];
    for (int i = tid; i < 2880; i += 320) s_ffw[i] = g_ffwc[i];

    // ---- Phase 1: pixel phasors (ringify is a no-op under sin/cos) ----
    const float* xb = x + (size_t)b * 784;
    for (int i = tid; i < 784; i += 320) {
        float s, c; sincosf(xb[i], &s, &c);
        s_z[i] = make_float2(c, s);
    }
    __syncthreads();

    // ---- Phase 2: ring conv1 (2x2 stride 2, 196 patches x 4 out-ch) ----
    for (int t = tid; t < 784; t += 320) {
        int p = t >> 2, c = t & 3;
        int i = p / 14, j = p % 14;
        int base = (i * 2) * 28 + j * 2;
        float2 z0 = s_z[base],      z1 = s_z[base + 1];
        float2 z2 = s_z[base + 28], z3 = s_z[base + 29];
        const float2* w = &s_w1[c * 4];
        float2 w0 = w[0], w1v = w[1], w2v = w[2], w3 = w[3];
        // a * conj(b): re = ax*bx + ay*by ; im = ay*bx - ax*by
        float Sx = z0.x * w0.x + z0.y * w0.y;
        float Sy = z0.y * w0.x - z0.x * w0.y;
        Sx += z1.x * w1v.x + z1.y * w1v.y;
        Sy += z1.y * w1v.x - z1.x * w1v.y;
        Sx += z2.x * w2v.x + z2.y * w2v.y;
        Sy += z2.y * w2v.x - z2.x * w2v.y;
        Sx += z3.x * w3.x + z3.y * w3.y;
        Sy += z3.y * w3.x - z3.x * w3.y;
        // e^{i atan2(Sy,Sx)} = (Sx,Sy)/|S|  -- no trig needed
        float inv = rsqrtf(fmaxf(Sx * Sx + Sy * Sy, 1e-36f));
        s_e1[c * 196 + p] = make_float2(Sx * inv, Sy * inv);
    }
    __syncthreads();

    // ---- Phase 3: ring conv2 (4x4x4 window, stride 2, 36 pos x 8 out-ch) ----
    if (tid < 288) {
        int pos = tid >> 3, o = tid & 7;
        int u = pos / 6, v = pos % 6;
        float Sx = 0.f, Sy = 0.f;
        #pragma unroll
        for (int c = 0; c < 4; c++) {
            #pragma unroll
            for (int di = 0; di < 4; di++) {
                int ebase = c * 196 + (2 * u + di) * 14 + 2 * v;
                int wbase = ((c * 4 + di) * 4) * 8 + o;
                #pragma unroll
                for (int dj = 0; dj < 4; dj++) {
                    float2 e = s_e1[ebase + dj];
                    float2 w = s_w2[wbase + dj * 8];
                    Sx += e.x * w.x + e.y * w.y;
                    Sy += e.y * w.x - e.x * w.y;
                }
            }
        }
        float inv = rsqrtf(fmaxf(Sx * Sx + Sy * Sy, 1e-36f));
        s_f[pos * 8 + o] = make_float2(Sx * inv, Sy * inv);
    }
    __syncthreads();

    // ---- Phase 4: ring FF. Warp n -> output n (10 warps), shuffle-reduce ----
    int wn = tid >> 5, l = tid & 31;
    float Sx = 0.f, Sy = 0.f;
    const float2* fw = &s_ffw[wn * 288];
    #pragma unroll
    for (int j = l; j < 288; j += 32) {
        float2 f = s_f[j];
        float2 ww = fw[j];
        Sx += f.x * ww.x + f.y * ww.y;
        Sy += f.y * ww.x - f.x * ww.y;
    }
    #pragma unroll
    for (int off = 16; off; off >>= 1) {
        Sx += __shfl_xor_sync(0xffffffff, Sx, off);
        Sy += __shfl_xor_sync(0xffffffff, Sy, off);
    }
    if (l == 0) {
        // sin(atan2(Sy,Sx)) = Sy / |S|
        float inv = rsqrtf(fmaxf(Sx * Sx + Sy * Sy, 1e-36f));
        out[b * 10 + wn] = Sy * inv;
    }
}

extern "C" void kernel_launch(void* const* d_in, const int* in_sizes, int n_in,
                              void* d_out, int out_size) {
    const float* x   = (const float*)d_in[0];   // [B,1,28,28]
    const float* w1  = (const float*)d_in[1];   // [4,1,2,2]
    const float* w2  = (const float*)d_in[2];   // [8,4,4,4]
    const float* ffw = (const float*)d_in[3];   // [288,10]
    float* out = (float*)d_out;                 // [B,10]
    int Bn = in_sizes[0] / 784;

    precompute_weights<<<1, 512>>>(w1, w2, ffw);
    ringnn_kernel<<<Bn, 320>>>(x, out);
}

// round 2
// speedup vs baseline: 1.2159x; 1.2159x over previous
#include <cuda_runtime.h>

// Precomputed conj-weight unit phasors (cos w, sin w); conj applied at use site.
__device__ __align__(16) float2 g_w1c[16];     // [o][k], k = di*2+dj
// conv2 weights packed for float4 dj-pair loads:
// float4 index f4 = ((c*4+di)*2 + dj/2)*8 + o ; float2 slot = f4*2 + (dj&1)
__device__ __align__(16) float2 g_w2c[512];
__device__ __align__(16) float2 g_ffwc[2880];  // [n][j], j contiguous per output n

__global__ void precompute_weights(const float* __restrict__ w1,
                                   const float* __restrict__ w2,
                                   const float* __restrict__ ffw) {
    int t = threadIdx.x;
    if (t < 16) {
        float s, c; sincosf(w1[t], &s, &c);
        g_w1c[t] = make_float2(c, s);
    }
    for (int i = t; i < 512; i += blockDim.x) {
        // conv2_w row-major [o][c][di][dj]
        int o = i >> 6, r = i & 63;
        int cc = r >> 4, di = (r >> 2) & 3, dj = r & 3;
        float s, c; sincosf(w2[i], &s, &c);
        int f4 = ((cc * 4 + di) * 2 + (dj >> 1)) * 8 + o;
        g_w2c[f4 * 2 + (dj & 1)] = make_float2(c, s);
    }
    for (int i = t; i < 2880; i += blockDim.x) {
        // ff_w row-major [j][n] -> store [n][j]
        int j = i / 10, n = i % 10;
        float s, c; sincosf(ffw[i], &s, &c);
        g_ffwc[n * 288 + j] = make_float2(c, s);
    }
}

__global__ __launch_bounds__(320, 6)
void ringnn_kernel(const float* __restrict__ x, float* __restrict__ out) {
    __shared__ float4 s_z[392];                 // pixel phasor pairs (2 pixels / float4)
    __shared__ __align__(16) float2 s_e1[784];  // conv1 out, [c][i][j] = c*196+i*14+j
    __shared__ float4 s_f4[144];                // conv2 out, j-pairs
    __shared__ float4 s_w1[8];                  // conv1 weight phasors (pairs)
    __shared__ float4 s_w2[256];                // conv2 weight phasors (dj-pairs, o fastest)

    const int tid = threadIdx.x;
    const int b = blockIdx.x;

    // Stage small weight tables into smem (vectorized)
    if (tid < 8)   s_w1[tid] = ((const float4*)g_w1c)[tid];
    if (tid < 256) s_w2[tid] = ((const float4*)g_w2c)[tid];

    // ---- Phase 1: pixel phasors (ringify is a no-op under sin/cos) ----
    const float4* xb4 = (const float4*)(x + (size_t)b * 784);
    for (int i = tid; i < 196; i += 320) {
        float4 xv = __ldg(xb4 + i);
        float s0, c0, s1, c1, s2, c2, s3, c3;
        __sincosf(xv.x, &s0, &c0);
        __sincosf(xv.y, &s1, &c1);
        __sincosf(xv.z, &s2, &c2);
        __sincosf(xv.w, &s3, &c3);
        s_z[2 * i]     = make_float4(c0, s0, c1, s1);
        s_z[2 * i + 1] = make_float4(c2, s2, c3, s3);
    }
    __syncthreads();

    // ---- Phase 2: ring conv1 (2x2 stride 2; thread = (patch, out-ch)) ----
    for (int t = tid; t < 784; t += 320) {
        int p = t >> 2, c = t & 3;
        int i = p / 14, j = p % 14;
        // pixels (2i,2j),(2i,2j+1) and (2i+1,2j),(2i+1,2j+1): float4 pair indices
        float4 za = s_z[i * 28 + j];        // z0 (x,y), z1 (z,w)
        float4 zb = s_z[i * 28 + 14 + j];   // z2, z3
        float4 wa = s_w1[c * 2];            // w0, w1
        float4 wb = s_w1[c * 2 + 1];        // w2, w3
        // a * conj(b): re = ax*bx + ay*by ; im = ay*bx - ax*by
        float Sx = za.x * wa.x + za.y * wa.y + za.z * wa.z + za.w * wa.w
                 + zb.x * wb.x + zb.y * wb.y + zb.z * wb.z + zb.w * wb.w;
        float Sy = za.y * wa.x - za.x * wa.y + za.w * wa.z - za.z * wa.w
                 + zb.y * wb.x - zb.x * wb.y + zb.w * wb.z - zb.z * wb.w;
        float inv = rsqrtf(fmaxf(Sx * Sx + Sy * Sy, 1e-36f));
        s_e1[c * 196 + p] = make_float2(Sx * inv, Sy * inv);
    }
    __syncthreads();

    // ---- Phase 3: ring conv2 (4x4x4 window, stride 2; thread = (pos, out-ch)) ----
    if (tid < 288) {
        int pos = tid >> 3, o = tid & 7;
        int u = pos / 6, v = pos % 6;
        float Sx = 0.f, Sy = 0.f;
        const float4* e4 = (const float4*)s_e1;
        #pragma unroll
        for (int c = 0; c < 4; c++) {
            #pragma unroll
            for (int di = 0; di < 4; di++) {
                int eb = (c * 196 + (2 * u + di) * 14 + 2 * v) >> 1;  // even ✓
                int wb = ((c * 4 + di) * 2) * 8 + o;
                #pragma unroll
                for (int djp = 0; djp < 2; djp++) {
                    float4 e = e4[eb + djp];
                    float4 w = s_w2[wb + djp * 8];
                    Sx += e.x * w.x + e.y * w.y + e.z * w.z + e.w * w.w;
                    Sy += e.y * w.x - e.x * w.y + e.w * w.z - e.z * w.w;
                }
            }
        }
        float inv = rsqrtf(fmaxf(Sx * Sx + Sy * Sy, 1e-36f));
        ((float2*)s_f4)[pos * 8 + o] = make_float2(Sx * inv, Sy * inv);
    }
    __syncthreads();

    // ---- Phase 4: ring FF. Warp n -> output n; FF weights straight from L1 ----
    int wn = tid >> 5, l = tid & 31;
    const float4* fw4 = (const float4*)g_ffwc + wn * 144;
    float Sx = 0.f, Sy = 0.f;
    for (int pi = l; pi < 144; pi += 32) {
        float4 f = s_f4[pi];
        float4 w = __ldg(fw4 + pi);
        Sx += f.x * w.x + f.y * w.y + f.z * w.z + f.w * w.w;
        Sy += f.y * w.x - f.x * w.y + f.w * w.z - f.z * w.w;
    }
    #pragma unroll
    for (int off = 16; off; off >>= 1) {
        Sx += __shfl_xor_sync(0xffffffff, Sx, off);
        Sy += __shfl_xor_sync(0xffffffff, Sy, off);
    }
    if (l == 0) {
        // sin(atan2(Sy,Sx)) = Sy / |S|
        float inv = rsqrtf(fmaxf(Sx * Sx + Sy * Sy, 1e-36f));
        out[b * 10 + wn] = Sy * inv;
    }
}

extern "C" void kernel_launch(void* const* d_in, const int* in_sizes, int n_in,
                              void* d_out, int out_size) {
    const float* x   = (const float*)d_in[0];   // [B,1,28,28]
    const float* w1  = (const float*)d_in[1];   // [4,1,2,2]
    const float* w2  = (const float*)d_in[2];   // [8,4,4,4]
    const float* ffw = (const float*)d_in[3];   // [288,10]
    float* out = (float*)d_out;                 // [B,10]
    int Bn = in_sizes[0] / 784;

    precompute_weights<<<1, 512>>>(w1, w2, ffw);
    ringnn_kernel<<<Bn, 320>>>(x, out);
}